// round 1
// baseline (speedup 1.0000x reference)
#include <cuda_runtime.h>

// Problem constants
#define BATCH 64
#define FEAT  784
#define DIM   1001
#define DIMSQ (DIM * DIM)          // 1002001
// out elements = 64 * 1001 * 1001 = 64,128,064 (divisible by 4)

// Scratch for the normalized state vectors (allocations are forbidden).
__device__ float g_state[BATCH * FEAT];

// ---------------------------------------------------------------------------
// Kernel 1: per-batch L2 norm + write normalized features to g_state.
// 64 blocks x 256 threads; ~200 KB traffic, negligible cost.
// ---------------------------------------------------------------------------
__global__ void norm_kernel(const float* __restrict__ x) {
    const int b   = blockIdx.x;
    const int tid = threadIdx.x;
    const float* xb = x + b * FEAT;

    float partial = 0.0f;
    for (int j = tid; j < FEAT; j += blockDim.x) {
        float v = xb[j];
        partial += v * v;
    }
    // warp reduce
    #pragma unroll
    for (int o = 16; o > 0; o >>= 1)
        partial += __shfl_xor_sync(0xFFFFFFFFu, partial, o);

    __shared__ float warpsum[8];
    __shared__ float s_inv;
    const int lane = tid & 31;
    const int w    = tid >> 5;
    if (lane == 0) warpsum[w] = partial;
    __syncthreads();
    if (tid == 0) {
        float s = 0.0f;
        #pragma unroll
        for (int i = 0; i < 8; i++) s += warpsum[i];
        s_inv = rsqrtf(s);
    }
    __syncthreads();

    const float inv = s_inv;
    for (int j = tid; j < FEAT; j += blockDim.x)
        g_state[b * FEAT + j] = xb[j] * inv;
}

// ---------------------------------------------------------------------------
// Kernel 2: stream the outer products. Flat float4 grid-stride.
// out[b,i,j] = (i<784 && j<784) ? s[b][i]*s[b][j] : 0
// Flat float4 stores are always 16B aligned (quad index * 16B).
// ---------------------------------------------------------------------------
__global__ void __launch_bounds__(256) outer_kernel(float4* __restrict__ out,
                                                    unsigned n4) {
    const unsigned stride = gridDim.x * blockDim.x;
    for (unsigned q = blockIdx.x * blockDim.x + threadIdx.x; q < n4; q += stride) {
        const unsigned e   = q * 4u;
        const unsigned b   = e / (unsigned)DIMSQ;          // const-div -> mul.hi
        const unsigned rem = e - b * (unsigned)DIMSQ;
        const unsigned i   = rem / (unsigned)DIM;
        const unsigned j   = rem - i * (unsigned)DIM;

        float4 v;
        if (j + 3u < (unsigned)DIM) {
            // Whole quad inside one row (also implies one batch). ~99.6% of quads.
            if (i >= (unsigned)FEAT) {
                v = make_float4(0.f, 0.f, 0.f, 0.f);      // zero row
            } else {
                const float* sb = g_state + b * FEAT;
                const float  si = sb[i];
                v.x = (j + 0u < (unsigned)FEAT) ? si * sb[j + 0u] : 0.f;
                v.y = (j + 1u < (unsigned)FEAT) ? si * sb[j + 1u] : 0.f;
                v.z = (j + 2u < (unsigned)FEAT) ? si * sb[j + 2u] : 0.f;
                v.w = (j + 3u < (unsigned)FEAT) ? si * sb[j + 3u] : 0.f;
            }
        } else {
            // Quad straddles a row (and possibly batch) boundary — full per-lane math.
            float vals[4];
            #pragma unroll
            for (int k = 0; k < 4; k++) {
                const unsigned ee = e + (unsigned)k;
                const unsigned bb = ee / (unsigned)DIMSQ;
                const unsigned r2 = ee - bb * (unsigned)DIMSQ;
                const unsigned ii = r2 / (unsigned)DIM;
                const unsigned jj = r2 - ii * (unsigned)DIM;
                vals[k] = (ii < (unsigned)FEAT && jj < (unsigned)FEAT)
                              ? g_state[bb * FEAT + ii] * g_state[bb * FEAT + jj]
                              : 0.f;
            }
            v = make_float4(vals[0], vals[1], vals[2], vals[3]);
        }
        out[q] = v;
    }
}

// ---------------------------------------------------------------------------
extern "C" void kernel_launch(void* const* d_in, const int* in_sizes, int n_in,
                              void* d_out, int out_size) {
    const float* x = (const float*)d_in[0];
    float* out = (float*)d_out;

    norm_kernel<<<BATCH, 256>>>(x);

    const unsigned n4 = (unsigned)(out_size / 4);  // 16,032,016 exactly
    // One full-occupancy wave: 148 SMs * 8 CTAs (256 thr) = 1184 CTAs.
    const int blocks = 1184;
    outer_kernel<<<blocks, 256>>>((float4*)out, n4);
}